// round 14
// baseline (speedup 1.0000x reference)
#include <cuda_runtime.h>
#include <cuda_fp16.h>
#include <cstdint>

#define Bc     4
#define Nc     1024
#define Hc     8
#define Dc     64
#define DIMc   512
#define INNERc 512
#define QKV3c  1536
#define BHc    32
#define KKc    716
#define SCALEc 0.125f

// Scratch (device globals: no allocations allowed)
__device__ __half g_xh[Bc * Nc * DIMc], g_xl[Bc * Nc * DIMc];      // x split
__device__ __half g_wqh[QKV3c * DIMc], g_wql[QKV3c * DIMc];        // w_qkv^T split [n][k]
__device__ __half g_wo[DIMc * INNERc];                             // w_out^T fp16 [n][k]
__device__ __half g_qh[Bc * Nc * INNERc], g_ql[Bc * Nc * INNERc];  // Q*scale split
__device__ __half g_kh[Bc * Nc * INNERc], g_kl[Bc * Nc * INNERc];  // K split
__device__ __half g_vt[(size_t)BHc * Dc * Nc];                     // V^T [bh][d][n]
__device__ __half g_p[(size_t)BHc * Nc * Nc];                      // fp16 post-softmax
__device__ __half g_att[Bc * Nc * INNERc];                         // fp16

// ---------------------------------------------------------------------------
// helpers
// ---------------------------------------------------------------------------
__device__ __forceinline__ void split_h(float v, __half& hi, __half& lo) {
    __half h = __float2half_rn(v);
    hi = h;
    lo = __float2half_rn(v - __half2float(h));
}
__device__ __forceinline__ void mma16(float* c, const unsigned* a,
                                      unsigned b0, unsigned b1) {
    asm volatile(
        "mma.sync.aligned.m16n8k16.row.col.f32.f16.f16.f32 "
        "{%0,%1,%2,%3}, {%4,%5,%6,%7}, {%8,%9}, {%0,%1,%2,%3};"
        : "+f"(c[0]), "+f"(c[1]), "+f"(c[2]), "+f"(c[3])
        : "r"(a[0]), "r"(a[1]), "r"(a[2]), "r"(a[3]), "r"(b0), "r"(b1));
}
__device__ __forceinline__ unsigned f2o(float x) {
    unsigned u = __float_as_uint(x);
    return (u & 0x80000000u) ? ~u : (u | 0x80000000u);
}
__device__ __forceinline__ float o2f(unsigned u) {
    unsigned f = (u & 0x80000000u) ? (u & 0x7fffffffu) : ~u;
    return __uint_as_float(f);
}
__device__ __forceinline__ uint32_t s2u(const void* p) {
    uint32_t a;
    asm("{ .reg .u64 t; cvta.to.shared.u64 t, %1; cvt.u32.u64 %0, t; }"
        : "=r"(a) : "l"(p));
    return a;
}
#define CP16(sa, gp) \
    asm volatile("cp.async.cg.shared.global [%0], [%1], 16;" :: "r"(sa), "l"(gp))
#define CPCOMMIT() asm volatile("cp.async.commit_group;")
#define CPWAIT1()  asm volatile("cp.async.wait_group 1;")
#define CPWAIT0()  asm volatile("cp.async.wait_group 0;")
__device__ __forceinline__ void ldsm4(unsigned* r, uint32_t a) {
    asm volatile("ldmatrix.sync.aligned.m8n8.x4.shared.b16 {%0,%1,%2,%3}, [%4];"
                 : "=r"(r[0]), "=r"(r[1]), "=r"(r[2]), "=r"(r[3]) : "r"(a));
}

// ---------------------------------------------------------------------------
// Prep kernels: split/convert inputs once
// ---------------------------------------------------------------------------
__global__ __launch_bounds__(256) void k_prep_x(const float* __restrict__ x) {
    int idx = blockIdx.x * 256 + threadIdx.x;
    float4 v = ((const float4*)x)[idx];
    float vv[4] = {v.x, v.y, v.z, v.w};
    __half hh[4], ll[4];
#pragma unroll
    for (int i = 0; i < 4; i++) split_h(vv[i], hh[i], ll[i]);
    ((uint2*)g_xh)[idx] = *(uint2*)hh;
    ((uint2*)g_xl)[idx] = *(uint2*)ll;
}

__global__ __launch_bounds__(256) void k_prep_wq(const float* __restrict__ w) {
    __shared__ float t[32][33];
    const int tx = threadIdx.x & 31, ty = threadIdx.x >> 5;
    const int n0 = blockIdx.x * 32, k0 = blockIdx.y * 32;
#pragma unroll
    for (int i = 0; i < 4; i++)
        t[ty + i * 8][tx] = w[(size_t)(k0 + ty + i * 8) * QKV3c + n0 + tx];
    __syncthreads();
#pragma unroll
    for (int i = 0; i < 4; i++) {
        int n = n0 + ty + i * 8;
        float v = t[tx][ty + i * 8];
        __half h, l;
        split_h(v, h, l);
        g_wqh[(size_t)n * DIMc + k0 + tx] = h;
        g_wql[(size_t)n * DIMc + k0 + tx] = l;
    }
}

__global__ __launch_bounds__(256) void k_prep_wo(const float* __restrict__ w) {
    __shared__ float t[32][33];
    const int tx = threadIdx.x & 31, ty = threadIdx.x >> 5;
    const int n0 = blockIdx.x * 32, k0 = blockIdx.y * 32;
#pragma unroll
    for (int i = 0; i < 4; i++)
        t[ty + i * 8][tx] = w[(size_t)(k0 + ty + i * 8) * DIMc + n0 + tx];
    __syncthreads();
#pragma unroll
    for (int i = 0; i < 4; i++) {
        int n = n0 + ty + i * 8;
        g_wo[(size_t)n * INNERc + k0 + tx] = __float2half(t[tx][ty + i * 8]);
    }
}

// ---------------------------------------------------------------------------
// Kernel 1: qkv GEMM, fp16-split, cp.async 2-stage + ldmatrix
// V-section CTAs use 2 products; Q/K use 3.
// ---------------------------------------------------------------------------
#define QK_ARR 10240      // 128 rows * 80 B
#define QK_STG (4 * QK_ARR)
#define QK_SMEM (2 * QK_STG)

__global__ __launch_bounds__(256, 2) void k_qkv() {
    extern __shared__ char sm[];
    const uint32_t sb = s2u(sm);
    const int tid = threadIdx.x, lane = tid & 31, wrp = tid >> 5;
    const int wm = wrp & 1, wn = wrp >> 1;
    const int tig = lane & 3, grp = lane >> 2;
    const int row0 = blockIdx.y * 128, col0 = blockIdx.x * 128;
    const bool isV = (blockIdx.x >> 2) == 2;
    float acc[4][4][4] = {};

    const int lrow = tid >> 2, lq = tid & 3;
    const uint32_t a_row = (lane & 7) + ((lane >> 3) & 1) * 8;
    const uint32_t a_kof = (lane >> 4) * 8;
    const uint32_t b_row = (lane & 7) + ((lane >= 16) ? 8 : 0);
    const uint32_t b_kof = ((lane >> 3) & 1) * 8;

    auto load_stage = [&](int c, int st) {
        const uint32_t s0 = sb + st * QK_STG;
        const int kt = c * 32;
#pragma unroll
        for (int it = 0; it < 2; it++) {
            int row = lrow + it * 64;
            uint32_t so = row * 80 + lq * 16;
            size_t ga = (size_t)(row0 + row) * DIMc + kt + lq * 8;
            CP16(s0 + so, g_xh + ga);
            CP16(s0 + QK_ARR + so, g_xl + ga);
            size_t gb = (size_t)(col0 + row) * DIMc + kt + lq * 8;
            CP16(s0 + 2 * QK_ARR + so, g_wqh + gb);
            CP16(s0 + 3 * QK_ARR + so, g_wql + gb);
        }
        CPCOMMIT();
    };
    load_stage(0, 0);
    load_stage(1, 1);

    for (int c = 0; c < 16; c++) {
        if (c < 15) { CPWAIT1(); } else { CPWAIT0(); }
        __syncthreads();
        const uint32_t s0 = sb + (c & 1) * QK_STG;
#pragma unroll
        for (int kk = 0; kk < 32; kk += 16) {
            unsigned ah[4][4], al[4][4];
#pragma unroll
            for (int f = 0; f < 4; f++) {
                uint32_t ra = s0 + (wm * 64 + f * 16 + a_row) * 80 + (kk + a_kof) * 2;
                ldsm4(ah[f], ra);
                ldsm4(al[f], ra + QK_ARR);
            }
            unsigned bh[2][4], bl[2][4];
#pragma unroll
            for (int gp = 0; gp < 2; gp++) {
                uint32_t rb = s0 + 2 * QK_ARR +
                              (wn * 32 + gp * 16 + b_row) * 80 + (kk + b_kof) * 2;
                ldsm4(bh[gp], rb);
                ldsm4(bl[gp], rb + QK_ARR);
            }
#pragma unroll
            for (int g = 0; g < 4; g++) {
                unsigned h0 = bh[g >> 1][(g & 1) * 2], h1 = bh[g >> 1][(g & 1) * 2 + 1];
                unsigned l0 = bl[g >> 1][(g & 1) * 2], l1 = bl[g >> 1][(g & 1) * 2 + 1];
#pragma unroll
                for (int f = 0; f < 4; f++) {
                    mma16(acc[f][g], ah[f], h0, h1);
                    if (!isV) mma16(acc[f][g], ah[f], l0, l1);
                    mma16(acc[f][g], al[f], h0, h1);
                }
            }
        }
        __syncthreads();
        if (c + 2 < 16) load_stage(c + 2, c & 1);
    }

    const int sec = blockIdx.x >> 2;            // 0=Q, 1=K, 2=V
    const int csec = (blockIdx.x & 3) * 128;
#pragma unroll
    for (int f = 0; f < 4; f++) {
        int row = row0 + wm * 64 + f * 16 + grp;
#pragma unroll
        for (int g = 0; g < 4; g++) {
            int cl = csec + wn * 32 + g * 8 + tig * 2;
            if (sec == 0) {
                __half h0, l0, h1, l1, h2, l2, h3, l3;
                split_h(acc[f][g][0] * SCALEc, h0, l0);
                split_h(acc[f][g][1] * SCALEc, h1, l1);
                split_h(acc[f][g][2] * SCALEc, h2, l2);
                split_h(acc[f][g][3] * SCALEc, h3, l3);
                *(__half2*)&g_qh[(size_t)row * INNERc + cl] = __halves2half2(h0, h1);
                *(__half2*)&g_ql[(size_t)row * INNERc + cl] = __halves2half2(l0, l1);
                *(__half2*)&g_qh[(size_t)(row + 8) * INNERc + cl] = __halves2half2(h2, h3);
                *(__half2*)&g_ql[(size_t)(row + 8) * INNERc + cl] = __halves2half2(l2, l3);
            } else if (sec == 1) {
                __half h0, l0, h1, l1, h2, l2, h3, l3;
                split_h(acc[f][g][0], h0, l0);
                split_h(acc[f][g][1], h1, l1);
                split_h(acc[f][g][2], h2, l2);
                split_h(acc[f][g][3], h3, l3);
                *(__half2*)&g_kh[(size_t)row * INNERc + cl] = __halves2half2(h0, h1);
                *(__half2*)&g_kl[(size_t)row * INNERc + cl] = __halves2half2(l0, l1);
                *(__half2*)&g_kh[(size_t)(row + 8) * INNERc + cl] = __halves2half2(h2, h3);
                *(__half2*)&g_kl[(size_t)(row + 8) * INNERc + cl] = __halves2half2(l2, l3);
            } else {
                int h = cl >> 6, d = cl & 63;
                int b = row >> 10, n = row & 1023;
                size_t base = ((size_t)(b * 8 + h) * 64 + d) * 1024 + n;
                g_vt[base]            = __float2half(acc[f][g][0]);
                g_vt[base + 1024]     = __float2half(acc[f][g][1]);
                g_vt[base + 8]        = __float2half(acc[f][g][2]);
                g_vt[base + 1024 + 8] = __float2half(acc[f][g][3]);
            }
        }
    }
}

// ---------------------------------------------------------------------------
// Kernel 2 (FUSED, wide): 32 query rows x full 1024 cols per CTA.
// Phase 1: dots via hoisted-A fp16-split MMA -> smem (32 x 1028 fp32).
// Phase 2: warp-per-row radix top-k + softmax from smem -> g_p.
// 1 CTA/SM (214.5 KB smem); registers unconstrained.
// ---------------------------------------------------------------------------
#define DT_KSTG  36864                 // per stage: Kh 128*144 + Kl 128*144
#define DT_KBASE 131584                // after dots (32*1028*4)
#define DT_Q     205312                // Qh 32*144=4608, Ql 4608
#define DT_HIST  205312                // reuse of Q region in phase 2
#define DT_CAND  213504
#define DT_GC    214528
#define DT_SMEM  214560

__global__ __launch_bounds__(256, 1) void k_dtopk() {
    extern __shared__ char sm[];
    const uint32_t sb = s2u(sm);
    const int tid = threadIdx.x, lane = tid & 31, w = tid >> 5;
    const int tig = lane & 3, grp = lane >> 2;
    const int bh_ = blockIdx.y, b = bh_ >> 3, h = bh_ & 7;
    const int i0 = blockIdx.x * 32;
    const unsigned FULL = 0xffffffffu;

    const uint32_t a_row = (lane & 7) + ((lane >> 3) & 1) * 8;
    const uint32_t a_kof = (lane >> 4) * 8;
    const uint32_t b_row = (lane & 7) + ((lane >= 16) ? 8 : 0);
    const uint32_t b_kof = ((lane >> 3) & 1) * 8;

    // Q load (32 rows x 8 c8-groups = 256 slots), committed with K chunk 0
    {
        int row = tid >> 3, c8 = tid & 7;
        size_t gq = (size_t)(b * Nc + i0 + row) * INNERc + h * Dc + c8 * 8;
        CP16(sb + DT_Q + row * 144 + c8 * 16, g_qh + gq);
        CP16(sb + DT_Q + 4608 + row * 144 + c8 * 16, g_ql + gq);
    }
    auto load_k = [&](int nc, int st) {
        const uint32_t kb = sb + DT_KBASE + st * DT_KSTG;
#pragma unroll
        for (int it = 0; it < 4; it++) {
            int idx = tid + it * 256;
            int n = idx >> 3, c8 = idx & 7;
            size_t gk = (size_t)(b * Nc + nc * 128 + n) * INNERc + h * Dc + c8 * 8;
            CP16(kb + n * 144 + c8 * 16, g_kh + gk);
            CP16(kb + 18432 + n * 144 + c8 * 16, g_kl + gk);
        }
        CPCOMMIT();
    };
    load_k(0, 0);
    load_k(1, 1);

    unsigned ah[2][4][4], al[2][4][4];   // hoisted Q fragments (2 m x 4 k, hi/lo)
    float* dots = (float*)sm;

    // ---- Phase 1: dots ----
    for (int nc = 0; nc < 8; nc++) {
        if (nc < 7) { CPWAIT1(); } else { CPWAIT0(); }
        __syncthreads();
        if (nc == 0) {
#pragma unroll
            for (int f = 0; f < 2; f++)
#pragma unroll
                for (int kk = 0; kk < 4; kk++) {
                    uint32_t ra = sb + DT_Q + (f * 16 + a_row) * 144 + (kk * 16 + a_kof) * 2;
                    ldsm4(ah[f][kk], ra);
                    ldsm4(al[f][kk], ra + 4608);
                }
        }
        const uint32_t kb = sb + DT_KBASE + (nc & 1) * DT_KSTG;
        float acc[2][2][4] = {};
#pragma unroll
        for (int kk = 0; kk < 4; kk++) {
            unsigned bh4[4], bl4[4];
            uint32_t rb = kb + (w * 16 + b_row) * 144 + (kk * 16 + b_kof) * 2;
            ldsm4(bh4, rb);
            ldsm4(bl4, rb + 18432);
#pragma unroll
            for (int g = 0; g < 2; g++) {
                unsigned h0 = bh4[g * 2], h1 = bh4[g * 2 + 1];
                unsigned l0 = bl4[g * 2], l1 = bl4[g * 2 + 1];
#pragma unroll
                for (int f = 0; f < 2; f++) {
                    mma16(acc[f][g], ah[f][kk], h0, h1);
                    mma16(acc[f][g], ah[f][kk], l0, l1);
                    mma16(acc[f][g], al[f][kk], h0, h1);
                }
            }
        }
#pragma unroll
        for (int f = 0; f < 2; f++)
#pragma unroll
            for (int g = 0; g < 2; g++) {
                int row = f * 16 + grp;
                int col = nc * 128 + w * 16 + g * 8 + tig * 2;
                *(float2*)&dots[row * 1028 + col] =
                    make_float2(acc[f][g][0], acc[f][g][1]);
                *(float2*)&dots[(row + 8) * 1028 + col] =
                    make_float2(acc[f][g][2], acc[f][g][3]);
            }
        __syncthreads();
        if (nc + 2 < 8) load_k(nc + 2, nc & 1);
    }
    __syncthreads();

    // ---- Phase 2: warp-per-row top-k + softmax (4 rows per warp) ----
    int* hist = (int*)(sm + DT_HIST);
    unsigned* cand = (unsigned*)(sm + DT_CAND);
    int* gcp = (int*)(sm + DT_GC);

#pragma unroll 1
    for (int rr = 0; rr < 4; rr++) {
        int r_idx = w * 4 + rr;
        float* drow = dots + r_idx * 1028;

        unsigned mn = 0xffffffffu, mx = 0u;
#pragma unroll
        for (int i = 0; i < 32; i++) {
            unsigned uu = f2o(drow[i * 32 + lane]);
            mn = min(mn, uu);
            mx = max(mx, uu);
        }
#pragma unroll
        for (int o = 16; o; o >>= 1) {
            mn = min(mn, __shfl_xor_sync(FULL, mn, o));
            mx = max(mx, __shfl_xor_sync(FULL, mx, o));
        }

        unsigned long long lo = mn;
        unsigned long long range = (unsigned long long)mx - mn + 1ull;
        int r = Nc - KKc;   // 308
        unsigned thr = mn;

        for (int pass = 0; pass < 6; pass++) {
            if (range == 1ull) { thr = (unsigned)lo; break; }
#pragma unroll
            for (int j = 0; j < 8; j++) hist[w * 256 + j * 32 + lane] = 0;
            __syncwarp();
            const unsigned lo32 = (unsigned)lo;
            const unsigned hi32 = (unsigned)(lo + range - 1ull);
            const bool small = (range <= 256ull);
            const unsigned mul = small ? 0u : (unsigned)((256ull << 32) / range);
#pragma unroll
            for (int i = 0; i < 32; i++) {
                unsigned uu = f2o(drow[i * 32 + lane]);
                if (uu >= lo32 && uu <= hi32) {
                    unsigned d = uu - lo32;
                    int bin = small ? (int)d : (int)__umulhi(d, mul);
                    atomicAdd(&hist[w * 256 + bin], 1);
                }
            }
            __syncwarp();
            int loc[8], s = 0;
#pragma unroll
            for (int j = 0; j < 8; j++) { loc[j] = hist[w * 256 + lane * 8 + j]; s += loc[j]; }
            int c = s;
#pragma unroll
            for (int o = 1; o < 32; o <<= 1) {
                int t = __shfl_up_sync(FULL, c, o);
                if (lane >= o) c += t;
            }
            int excl = c - s;
            unsigned bal = __ballot_sync(FULL, c > r);
            int L = __ffs(bal) - 1;
            int bkt = 0, r2 = 0, cnt = 0;
            if (lane == L) {
                int a2 = excl;
#pragma unroll
                for (int j = 0; j < 8; j++) {
                    if (a2 + loc[j] > r) { bkt = lane * 8 + j; r2 = r - a2; cnt = loc[j]; break; }
                    a2 += loc[j];
                }
            }
            bkt = __shfl_sync(FULL, bkt, L);
            r2  = __shfl_sync(FULL, r2, L);
            cnt = __shfl_sync(FULL, cnt, L);

            unsigned long long nlo, nhi;
            if (small) {
                nlo = lo + (unsigned)bkt;
                nhi = nlo;
            } else {
                unsigned long long dl = (((unsigned long long)bkt << 32) + mul - 1ull) / mul;
                unsigned long long dh = ((((unsigned long long)(bkt + 1)) << 32) + mul - 1ull) / mul - 1ull;
                if (dh > range - 1ull) dh = range - 1ull;
                nlo = lo + dl;
                nhi = lo + dh;
            }

            if (cnt <= 32) {
                if (lane == 0) gcp[w] = 0;
                __syncwarp();
                const unsigned glo = (unsigned)nlo, ghi = (unsigned)nhi;
#pragma unroll
                for (int i = 0; i < 32; i++) {
                    unsigned uu = f2o(drow[i * 32 + lane]);
                    if (uu >= glo && uu <= ghi) {
                        int p = atomicAdd(&gcp[w], 1);
                        cand[w * 32 + p] = uu;
                    }
                }
                __syncwarp();
                unsigned tu = 0;
                int rk = -1;
                if (lane < cnt) {
                    tu = cand[w * 32 + lane];
                    rk = 0;
                    for (int j = 0; j < cnt; j++) {
                        unsigned o2 = cand[w * 32 + j];
                        rk += (o2 < tu) || (o2 == tu && j < lane);
                    }
                }
                unsigned who = __ballot_sync(FULL, rk == r2);
                thr = __shfl_sync(FULL, tu, __ffs(who) - 1);
                break;
            } else {
                lo = nlo;
                range = nhi - nlo + 1ull;
                r = r2;
            }
        }

        // masked softmax; write g_p (fp16)
        const float rmax = o2f(mx);
        float sum = 0.f;
#pragma unroll
        for (int i = 0; i < 32; i++) {
            float v = drow[i * 32 + lane];
            unsigned uu = f2o(v);
            float e = (uu >= thr) ? __expf(v - rmax) : 0.f;
            drow[i * 32 + lane] = e;
            sum += e;
        }
#pragma unroll
        for (int o = 16; o; o >>= 1) sum += __shfl_xor_sync(FULL, sum, o);
        const float inv = 1.0f / sum;
        __half* pb = g_p + ((size_t)bh_ * Nc + i0 + r_idx) * Nc;
#pragma unroll
        for (int i = 0; i < 32; i++)
            pb[i * 32 + lane] = __float2half(drow[i * 32 + lane] * inv);
    }
}

// ---------------------------------------------------------------------------
// Kernel 4: att = P @ V, fp16 MMA, cp.async + ldmatrix (unchanged)
// ---------------------------------------------------------------------------
#define AV_P   18432
#define AV_STG (AV_P + 64 * 144)
#define AV_SMEM (2 * AV_STG)

__global__ __launch_bounds__(256, 2) void k_av() {
    extern __shared__ char sm[];
    const uint32_t sb = s2u(sm);
    const int tid = threadIdx.x, lane = tid & 31, wrp = tid >> 5;
    const int wm = wrp >> 1, wn = wrp & 1;
    const int tig = lane & 3, grp = lane >> 2;
    const int bh_ = blockIdx.y, b = bh_ >> 3, h = bh_ & 7;
    const int i0 = blockIdx.x * 128;
    const __half* pg = g_p + ((size_t)bh_ * Nc + i0) * Nc;
    const __half* vt = g_vt + (size_t)bh_ * Dc * Nc;
    float acc[2][4][4] = {};

    const uint32_t a_row = (lane & 7) + ((lane >> 3) & 1) * 8;
    const uint32_t a_kof = (lane >> 4) * 8;
    const uint32_t b_row = (lane & 7) + ((lane >= 16) ? 8 : 0);
    const uint32_t b_kof = ((lane >> 3) & 1) * 8;

    auto load_stage = [&](int c, int st) {
        const uint32_t s0 = sb + st * AV_STG;
        const int kc = c * 64;
#pragma unroll
        for (int it = 0; it < 4; it++) {
            int idx = tid + it * 256;
            int row = idx >> 3, c8 = idx & 7;
            CP16(s0 + row * 144 + c8 * 16, pg + (size_t)row * Nc + kc + c8 * 8);
        }
#pragma unroll
        for (int it = 0; it < 2; it++) {
            int idx = tid + it * 256;
            int d = idx >> 3, c8 = idx & 7;
            CP16(s0 + AV_P + d * 144 + c8 * 16, vt + (size_t)d * Nc + kc + c8 * 8);
        }
        CPCOMMIT();
    };
    load_stage(0, 0);
    load_stage(1, 1);

    for (int c = 0; c < 16; c++) {
        if (c < 15) { CPWAIT1(); } else { CPWAIT0(); }
        __syncthreads();
        const uint32_t s0 = sb + (c & 1) * AV_STG;
#pragma unroll
        for (int kk = 0; kk < 64; kk += 16) {
            unsigned a[2][4];
#pragma unroll
            for (int f = 0; f < 2; f++) {
                uint32_t ra = s0 + (wm * 32 + f * 16 + a_row) * 144 + (kk + a_kof) * 2;
                ldsm4(a[f], ra);
            }
            unsigned bb[2][4];
#pragma unroll
            for (int gp = 0; gp < 2; gp++) {
                uint32_t rb = s0 + AV_P +
                              (wn * 32 + gp * 16 + b_row) * 144 + (kk + b_kof) * 2;
                ldsm4(bb[gp], rb);
            }
#pragma unroll
            for (int g = 0; g < 4; g++) {
                unsigned b0 = bb[g >> 1][(g & 1) * 2], b1 = bb[g >> 1][(g & 1) * 2 + 1];
#pragma unroll
                for (int f = 0; f < 2; f++) mma16(acc[f][g], a[f], b0, b1);
            }
        }
        __syncthreads();
        if (c + 2 < 16) load_stage(c + 2, c & 1);
    }
#pragma unroll
    for (int f = 0; f < 2; f++) {
        int rr = b * Nc + i0 + wm * 32 + f * 16 + grp;
#pragma unroll
        for (int g = 0; g < 4; g++) {
            int col = h * Dc + wn * 32 + g * 8 + tig * 2;
            __half2 h0 = __floats2half2_rn(acc[f][g][0], acc[f][g][1]);
            __half2 h1 = __floats2half2_rn(acc[f][g][2], acc[f][g][3]);
            *(__half2*)&g_att[rr * INNERc + col] = h0;
            *(__half2*)&g_att[(rr + 8) * INNERc + col] = h1;
        }
    }
}

// ---------------------------------------------------------------------------
// Kernel 5: out = att @ w_out + b_out; 128m x 64n tiles (full wave)
// ---------------------------------------------------------------------------
#define KO_A   18432
#define KO_STG (KO_A + 64 * 144)
#define KO_SMEM (2 * KO_STG)

__global__ __launch_bounds__(256, 2) void k_out(const float* __restrict__ bias,
                                                float* __restrict__ out) {
    extern __shared__ char sm[];
    const uint32_t sb = s2u(sm);
    const int tid = threadIdx.x, lane = tid & 31, wrp = tid >> 5;
    const int wm = wrp >> 1, wn = wrp & 1;
    const int tig = lane & 3, grp = lane >> 2;
    const int row0 = blockIdx.x * 128, col0 = blockIdx.y * 64;
    float acc[2][4][4] = {};

    const uint32_t a_row = (lane & 7) + ((lane >> 3) & 1) * 8;
    const uint32_t a_kof = (lane >> 4) * 8;
    const uint32_t b_row = (lane & 7) + ((lane >= 16) ? 8 : 0);
    const uint32_t b_kof = ((lane >> 3) & 1) * 8;

    auto load_stage = [&](int c, int st) {
        const uint32_t s0 = sb + st * KO_STG;
        const int kc = c * 64;
#pragma unroll
        for (int it = 0; it < 4; it++) {
            int idx = tid + it * 256;
            int row = idx >> 3, c8 = idx & 7;
            CP16(s0 + row * 144 + c8 * 16,
                 g_att + (size_t)(row0 + row) * INNERc + kc + c8 * 8);
        }
#pragma unroll
        for (int it = 0; it < 2; it++) {
            int idx = tid + it * 256;
            int n = idx >> 3, c8 = idx & 7;
            CP16(s0 + KO_A + n * 144 + c8 * 16,
                 g_wo + (size_t)(col0 + n) * INNERc + kc + c8 * 8);
        }
        CPCOMMIT();
    };
    load_stage(0, 0);
    load_stage(1, 1);

    for (int c = 0; c < 8; c++) {
        if (c < 7) { CPWAIT1(); } else { CPWAIT0(); }
        __syncthreads();
        const uint32_t s0 = sb + (c & 1) * KO_STG;
#pragma unroll
        for (int kk = 0; kk < 64; kk += 16) {
            unsigned a[2][4];
#pragma unroll
            for (int f = 0; f < 2; f++) {
                uint32_t ra = s0 + (wm * 32 + f * 16 + a_row) * 144 + (kk + a_kof) * 2;
                ldsm4(a[f], ra);
            }
            unsigned bb[2][4];
#pragma unroll
            for (int gp = 0; gp < 2; gp++) {
                uint32_t rb = s0 + KO_A +
                              (wn * 32 + gp * 16 + b_row) * 144 + (kk + b_kof) * 2;
                ldsm4(bb[gp], rb);
            }
#pragma unroll
            for (int g = 0; g < 4; g++) {
                unsigned b0 = bb[g >> 1][(g & 1) * 2], b1 = bb[g >> 1][(g & 1) * 2 + 1];
#pragma unroll
                for (int f = 0; f < 2; f++) mma16(acc[f][g], a[f], b0, b1);
            }
        }
        __syncthreads();
        if (c + 2 < 8) load_stage(c + 2, c & 1);
    }
#pragma unroll
    for (int f = 0; f < 2; f++) {
        int row = row0 + wm * 32 + f * 16 + grp;
#pragma unroll
        for (int g = 0; g < 4; g++) {
            int col = col0 + wn * 32 + g * 8 + tig * 2;
            float b0 = bias[col], b1 = bias[col + 1];
            *(float2*)&out[(size_t)row * DIMc + col] =
                make_float2(acc[f][g][0] + b0, acc[f][g][1] + b1);
            *(float2*)&out[(size_t)(row + 8) * DIMc + col] =
                make_float2(acc[f][g][2] + b0, acc[f][g][3] + b1);
        }
    }
}

// ---------------------------------------------------------------------------
extern "C" void kernel_launch(void* const* d_in, const int* in_sizes, int n_in,
                              void* d_out, int out_size) {
    const float* x     = (const float*)d_in[0];  // [4,1024,512]
    const float* w_qkv = (const float*)d_in[1];  // [512,1536]
    const float* w_out = (const float*)d_in[2];  // [512,512]
    const float* b_out = (const float*)d_in[3];  // [512]
    float* out = (float*)d_out;                  // [4,1024,512]

    cudaFuncSetAttribute(k_qkv, cudaFuncAttributeMaxDynamicSharedMemorySize, QK_SMEM);
    cudaFuncSetAttribute(k_dtopk, cudaFuncAttributeMaxDynamicSharedMemorySize, DT_SMEM);
    cudaFuncSetAttribute(k_av, cudaFuncAttributeMaxDynamicSharedMemorySize, AV_SMEM);
    cudaFuncSetAttribute(k_out, cudaFuncAttributeMaxDynamicSharedMemorySize, KO_SMEM);

    k_prep_x<<<(Bc * Nc * DIMc / 4) / 256, 256>>>(x);
    k_prep_wq<<<dim3(QKV3c / 32, DIMc / 32), 256>>>(w_qkv);
    k_prep_wo<<<dim3(DIMc / 32, INNERc / 32), 256>>>(w_out);
    k_qkv<<<dim3(QKV3c / 128, (Bc * Nc) / 128), 256, QK_SMEM>>>();
    k_dtopk<<<dim3(Nc / 32, BHc), 256, DT_SMEM>>>();
    k_av<<<dim3(Nc / 128, BHc), 256, AV_SMEM>>>();
    k_out<<<dim3((Bc * Nc) / 128, DIMc / 64), 256, KO_SMEM>>>(b_out, out);
}

// round 15
// speedup vs baseline: 1.5984x; 1.5984x over previous
#include <cuda_runtime.h>
#include <cuda_fp16.h>
#include <cstdint>

#define Bc     4
#define Nc     1024
#define Hc     8
#define Dc     64
#define DIMc   512
#define INNERc 512
#define QKV3c  1536
#define BHc    32
#define KKc    716
#define SCALEc 0.125f

// Scratch (device globals: no allocations allowed)
__device__ __half g_xh[Bc * Nc * DIMc], g_xl[Bc * Nc * DIMc];      // x split
__device__ __half g_wqh[QKV3c * DIMc], g_wql[QKV3c * DIMc];        // w_qkv^T split [n][k]
__device__ __half g_wo[DIMc * INNERc];                             // w_out^T fp16 [n][k]
__device__ __half g_qh[Bc * Nc * INNERc], g_ql[Bc * Nc * INNERc];  // Q*scale split
__device__ __half g_kh[Bc * Nc * INNERc], g_kl[Bc * Nc * INNERc];  // K split
__device__ __half g_vt[(size_t)BHc * Dc * Nc];                     // V^T [bh][d][n]
__device__ float  g_dots[(size_t)BHc * Nc * Nc];                   // fp32 pre-softmax
__device__ __half g_p[(size_t)BHc * Nc * Nc];                      // fp16 post-softmax
__device__ __half g_att[Bc * Nc * INNERc];                         // fp16

// ---------------------------------------------------------------------------
// helpers
// ---------------------------------------------------------------------------
__device__ __forceinline__ void split_h(float v, __half& hi, __half& lo) {
    __half h = __float2half_rn(v);
    hi = h;
    lo = __float2half_rn(v - __half2float(h));
}
__device__ __forceinline__ void mma16(float* c, const unsigned* a,
                                      unsigned b0, unsigned b1) {
    asm volatile(
        "mma.sync.aligned.m16n8k16.row.col.f32.f16.f16.f32 "
        "{%0,%1,%2,%3}, {%4,%5,%6,%7}, {%8,%9}, {%0,%1,%2,%3};"
        : "+f"(c[0]), "+f"(c[1]), "+f"(c[2]), "+f"(c[3])
        : "r"(a[0]), "r"(a[1]), "r"(a[2]), "r"(a[3]), "r"(b0), "r"(b1));
}
__device__ __forceinline__ unsigned f2o(float x) {
    unsigned u = __float_as_uint(x);
    return (u & 0x80000000u) ? ~u : (u | 0x80000000u);
}
__device__ __forceinline__ float o2f(unsigned u) {
    unsigned f = (u & 0x80000000u) ? (u & 0x7fffffffu) : ~u;
    return __uint_as_float(f);
}
__device__ __forceinline__ uint32_t s2u(const void* p) {
    uint32_t a;
    asm("{ .reg .u64 t; cvta.to.shared.u64 t, %1; cvt.u32.u64 %0, t; }"
        : "=r"(a) : "l"(p));
    return a;
}
#define CP16(sa, gp) \
    asm volatile("cp.async.cg.shared.global [%0], [%1], 16;" :: "r"(sa), "l"(gp))
#define CPCOMMIT() asm volatile("cp.async.commit_group;")
#define CPWAIT1()  asm volatile("cp.async.wait_group 1;")
#define CPWAIT0()  asm volatile("cp.async.wait_group 0;")
__device__ __forceinline__ void ldsm4(unsigned* r, uint32_t a) {
    asm volatile("ldmatrix.sync.aligned.m8n8.x4.shared.b16 {%0,%1,%2,%3}, [%4];"
                 : "=r"(r[0]), "=r"(r[1]), "=r"(r[2]), "=r"(r[3]) : "r"(a));
}

// ---------------------------------------------------------------------------
// Prep kernels: split/convert inputs once
// ---------------------------------------------------------------------------
__global__ __launch_bounds__(256) void k_prep_x(const float* __restrict__ x) {
    int idx = blockIdx.x * 256 + threadIdx.x;
    float4 v = ((const float4*)x)[idx];
    float vv[4] = {v.x, v.y, v.z, v.w};
    __half hh[4], ll[4];
#pragma unroll
    for (int i = 0; i < 4; i++) split_h(vv[i], hh[i], ll[i]);
    ((uint2*)g_xh)[idx] = *(uint2*)hh;
    ((uint2*)g_xl)[idx] = *(uint2*)ll;
}

__global__ __launch_bounds__(256) void k_prep_wq(const float* __restrict__ w) {
    __shared__ float t[32][33];
    const int tx = threadIdx.x & 31, ty = threadIdx.x >> 5;
    const int n0 = blockIdx.x * 32, k0 = blockIdx.y * 32;
#pragma unroll
    for (int i = 0; i < 4; i++)
        t[ty + i * 8][tx] = w[(size_t)(k0 + ty + i * 8) * QKV3c + n0 + tx];
    __syncthreads();
#pragma unroll
    for (int i = 0; i < 4; i++) {
        int n = n0 + ty + i * 8;
        float v = t[tx][ty + i * 8];
        __half h, l;
        split_h(v, h, l);
        g_wqh[(size_t)n * DIMc + k0 + tx] = h;
        g_wql[(size_t)n * DIMc + k0 + tx] = l;
    }
}

__global__ __launch_bounds__(256) void k_prep_wo(const float* __restrict__ w) {
    __shared__ float t[32][33];
    const int tx = threadIdx.x & 31, ty = threadIdx.x >> 5;
    const int n0 = blockIdx.x * 32, k0 = blockIdx.y * 32;
#pragma unroll
    for (int i = 0; i < 4; i++)
        t[ty + i * 8][tx] = w[(size_t)(k0 + ty + i * 8) * DIMc + n0 + tx];
    __syncthreads();
#pragma unroll
    for (int i = 0; i < 4; i++) {
        int n = n0 + ty + i * 8;
        g_wo[(size_t)n * INNERc + k0 + tx] = __float2half(t[tx][ty + i * 8]);
    }
}

// ---------------------------------------------------------------------------
// Kernel 1: qkv GEMM, fp16-split, cp.async 2-stage + ldmatrix
// V-section CTAs use 2 products; Q/K use 3.
// ---------------------------------------------------------------------------
#define QK_ARR 10240      // 128 rows * 80 B
#define QK_STG (4 * QK_ARR)
#define QK_SMEM (2 * QK_STG)

__global__ __launch_bounds__(256, 2) void k_qkv() {
    extern __shared__ char sm[];
    const uint32_t sb = s2u(sm);
    const int tid = threadIdx.x, lane = tid & 31, wrp = tid >> 5;
    const int wm = wrp & 1, wn = wrp >> 1;
    const int tig = lane & 3, grp = lane >> 2;
    const int row0 = blockIdx.y * 128, col0 = blockIdx.x * 128;
    const bool isV = (blockIdx.x >> 2) == 2;
    float acc[4][4][4] = {};

    const int lrow = tid >> 2, lq = tid & 3;
    const uint32_t a_row = (lane & 7) + ((lane >> 3) & 1) * 8;
    const uint32_t a_kof = (lane >> 4) * 8;
    const uint32_t b_row = (lane & 7) + ((lane >= 16) ? 8 : 0);
    const uint32_t b_kof = ((lane >> 3) & 1) * 8;

    auto load_stage = [&](int c, int st) {
        const uint32_t s0 = sb + st * QK_STG;
        const int kt = c * 32;
#pragma unroll
        for (int it = 0; it < 2; it++) {
            int row = lrow + it * 64;
            uint32_t so = row * 80 + lq * 16;
            size_t ga = (size_t)(row0 + row) * DIMc + kt + lq * 8;
            CP16(s0 + so, g_xh + ga);
            CP16(s0 + QK_ARR + so, g_xl + ga);
            size_t gb = (size_t)(col0 + row) * DIMc + kt + lq * 8;
            CP16(s0 + 2 * QK_ARR + so, g_wqh + gb);
            CP16(s0 + 3 * QK_ARR + so, g_wql + gb);
        }
        CPCOMMIT();
    };
    load_stage(0, 0);
    load_stage(1, 1);

    for (int c = 0; c < 16; c++) {
        if (c < 15) { CPWAIT1(); } else { CPWAIT0(); }
        __syncthreads();
        const uint32_t s0 = sb + (c & 1) * QK_STG;
#pragma unroll
        for (int kk = 0; kk < 32; kk += 16) {
            unsigned ah[4][4], al[4][4];
#pragma unroll
            for (int f = 0; f < 4; f++) {
                uint32_t ra = s0 + (wm * 64 + f * 16 + a_row) * 80 + (kk + a_kof) * 2;
                ldsm4(ah[f], ra);
                ldsm4(al[f], ra + QK_ARR);
            }
            unsigned bh[2][4], bl[2][4];
#pragma unroll
            for (int gp = 0; gp < 2; gp++) {
                uint32_t rb = s0 + 2 * QK_ARR +
                              (wn * 32 + gp * 16 + b_row) * 80 + (kk + b_kof) * 2;
                ldsm4(bh[gp], rb);
                ldsm4(bl[gp], rb + QK_ARR);
            }
#pragma unroll
            for (int g = 0; g < 4; g++) {
                unsigned h0 = bh[g >> 1][(g & 1) * 2], h1 = bh[g >> 1][(g & 1) * 2 + 1];
                unsigned l0 = bl[g >> 1][(g & 1) * 2], l1 = bl[g >> 1][(g & 1) * 2 + 1];
#pragma unroll
                for (int f = 0; f < 4; f++) {
                    mma16(acc[f][g], ah[f], h0, h1);
                    if (!isV) mma16(acc[f][g], ah[f], l0, l1);
                    mma16(acc[f][g], al[f], h0, h1);
                }
            }
        }
        __syncthreads();
        if (c + 2 < 16) load_stage(c + 2, c & 1);
    }

    const int sec = blockIdx.x >> 2;            // 0=Q, 1=K, 2=V
    const int csec = (blockIdx.x & 3) * 128;
#pragma unroll
    for (int f = 0; f < 4; f++) {
        int row = row0 + wm * 64 + f * 16 + grp;
#pragma unroll
        for (int g = 0; g < 4; g++) {
            int cl = csec + wn * 32 + g * 8 + tig * 2;
            if (sec == 0) {
                __half h0, l0, h1, l1, h2, l2, h3, l3;
                split_h(acc[f][g][0] * SCALEc, h0, l0);
                split_h(acc[f][g][1] * SCALEc, h1, l1);
                split_h(acc[f][g][2] * SCALEc, h2, l2);
                split_h(acc[f][g][3] * SCALEc, h3, l3);
                *(__half2*)&g_qh[(size_t)row * INNERc + cl] = __halves2half2(h0, h1);
                *(__half2*)&g_ql[(size_t)row * INNERc + cl] = __halves2half2(l0, l1);
                *(__half2*)&g_qh[(size_t)(row + 8) * INNERc + cl] = __halves2half2(h2, h3);
                *(__half2*)&g_ql[(size_t)(row + 8) * INNERc + cl] = __halves2half2(l2, l3);
            } else if (sec == 1) {
                __half h0, l0, h1, l1, h2, l2, h3, l3;
                split_h(acc[f][g][0], h0, l0);
                split_h(acc[f][g][1], h1, l1);
                split_h(acc[f][g][2], h2, l2);
                split_h(acc[f][g][3], h3, l3);
                *(__half2*)&g_kh[(size_t)row * INNERc + cl] = __halves2half2(h0, h1);
                *(__half2*)&g_kl[(size_t)row * INNERc + cl] = __halves2half2(l0, l1);
                *(__half2*)&g_kh[(size_t)(row + 8) * INNERc + cl] = __halves2half2(h2, h3);
                *(__half2*)&g_kl[(size_t)(row + 8) * INNERc + cl] = __halves2half2(l2, l3);
            } else {
                int h = cl >> 6, d = cl & 63;
                int b = row >> 10, n = row & 1023;
                size_t base = ((size_t)(b * 8 + h) * 64 + d) * 1024 + n;
                g_vt[base]            = __float2half(acc[f][g][0]);
                g_vt[base + 1024]     = __float2half(acc[f][g][1]);
                g_vt[base + 8]        = __float2half(acc[f][g][2]);
                g_vt[base + 1024 + 8] = __float2half(acc[f][g][3]);
            }
        }
    }
}

// ---------------------------------------------------------------------------
// Kernel 2: dots = (Q*scale) @ K^T, fp16-split, cp.async + ldmatrix
// block 128x128, D=64 in 2 BK=32 stages
// ---------------------------------------------------------------------------
__global__ __launch_bounds__(256, 2) void k_dots() {
    extern __shared__ char sm[];
    const uint32_t sb = s2u(sm);
    const int tid = threadIdx.x, lane = tid & 31, wrp = tid >> 5;
    const int wm = wrp & 1, wn = wrp >> 1;
    const int tig = lane & 3, grp = lane >> 2;
    const int bh_ = blockIdx.z, b = bh_ >> 3, h = bh_ & 7;
    const int i0 = blockIdx.y * 128, j0 = blockIdx.x * 128;
    float acc[4][4][4] = {};

    const int lrow = tid >> 2, lq = tid & 3;
    const uint32_t a_row = (lane & 7) + ((lane >> 3) & 1) * 8;
    const uint32_t a_kof = (lane >> 4) * 8;
    const uint32_t b_row = (lane & 7) + ((lane >= 16) ? 8 : 0);
    const uint32_t b_kof = ((lane >> 3) & 1) * 8;

    auto load_stage = [&](int c, int st) {
        const uint32_t s0 = sb + st * QK_STG;
        const int kt = c * 32;
#pragma unroll
        for (int it = 0; it < 2; it++) {
            int row = lrow + it * 64;
            uint32_t so = row * 80 + lq * 16;
            size_t ga = (size_t)(b * Nc + i0 + row) * INNERc + h * Dc + kt + lq * 8;
            CP16(s0 + so, g_qh + ga);
            CP16(s0 + QK_ARR + so, g_ql + ga);
            size_t gb = (size_t)(b * Nc + j0 + row) * INNERc + h * Dc + kt + lq * 8;
            CP16(s0 + 2 * QK_ARR + so, g_kh + gb);
            CP16(s0 + 3 * QK_ARR + so, g_kl + gb);
        }
        CPCOMMIT();
    };
    load_stage(0, 0);
    load_stage(1, 1);

    for (int c = 0; c < 2; c++) {
        if (c == 0) { CPWAIT1(); } else { CPWAIT0(); }
        __syncthreads();
        const uint32_t s0 = sb + c * QK_STG;
#pragma unroll
        for (int kk = 0; kk < 32; kk += 16) {
            unsigned ah[4][4], al[4][4];
#pragma unroll
            for (int f = 0; f < 4; f++) {
                uint32_t ra = s0 + (wm * 64 + f * 16 + a_row) * 80 + (kk + a_kof) * 2;
                ldsm4(ah[f], ra);
                ldsm4(al[f], ra + QK_ARR);
            }
            unsigned bh[2][4], bl[2][4];
#pragma unroll
            for (int gp = 0; gp < 2; gp++) {
                uint32_t rb = s0 + 2 * QK_ARR +
                              (wn * 32 + gp * 16 + b_row) * 80 + (kk + b_kof) * 2;
                ldsm4(bh[gp], rb);
                ldsm4(bl[gp], rb + QK_ARR);
            }
#pragma unroll
            for (int g = 0; g < 4; g++) {
                unsigned h0 = bh[g >> 1][(g & 1) * 2], h1 = bh[g >> 1][(g & 1) * 2 + 1];
                unsigned l0 = bl[g >> 1][(g & 1) * 2], l1 = bl[g >> 1][(g & 1) * 2 + 1];
#pragma unroll
                for (int f = 0; f < 4; f++) {
                    mma16(acc[f][g], ah[f], h0, h1);
                    mma16(acc[f][g], ah[f], l0, l1);
                    mma16(acc[f][g], al[f], h0, h1);
                }
            }
        }
        __syncthreads();
    }
    float* out = g_dots + (size_t)bh_ * Nc * Nc;
#pragma unroll
    for (int f = 0; f < 4; f++) {
        int row = i0 + wm * 64 + f * 16 + grp;
#pragma unroll
        for (int g = 0; g < 4; g++) {
            int col = j0 + wn * 32 + g * 8 + tig * 2;
            *(float2*)&out[(size_t)row * Nc + col] =
                make_float2(acc[f][g][0], acc[f][g][1]);
            *(float2*)&out[(size_t)(row + 8) * Nc + col] =
                make_float2(acc[f][g][2], acc[f][g][3]);
        }
    }
}

// ---------------------------------------------------------------------------
// Kernel 3: warp-per-row exact top-KK + masked softmax; 256-bin radix pass
// In-place exp (u[] reused) to minimize register pressure.
// ---------------------------------------------------------------------------
__global__ __launch_bounds__(256) void k_topk() {
    __shared__ int      hist[8][256];
    __shared__ unsigned cand[8][32];
    __shared__ int      gc[8];

    const unsigned FULL = 0xffffffffu;
    const int tid = threadIdx.x, lane = tid & 31, w = tid >> 5;
    const size_t row = (size_t)blockIdx.x * 8 + w;
    const float* base = g_dots + row * Nc;
    __half* pb = g_p + row * Nc;

    unsigned u[32];
#pragma unroll
    for (int c = 0; c < 8; c++) {
        float4 v4 = *(const float4*)&base[c * 128 + lane * 4];
        u[c * 4 + 0] = f2o(v4.x);
        u[c * 4 + 1] = f2o(v4.y);
        u[c * 4 + 2] = f2o(v4.z);
        u[c * 4 + 3] = f2o(v4.w);
    }

    unsigned mn = u[0], mx = u[0];
#pragma unroll
    for (int i = 1; i < 32; i++) { mn = min(mn, u[i]); mx = max(mx, u[i]); }
#pragma unroll
    for (int o = 16; o; o >>= 1) {
        mn = min(mn, __shfl_xor_sync(FULL, mn, o));
        mx = max(mx, __shfl_xor_sync(FULL, mx, o));
    }

    unsigned long long lo = mn;
    unsigned long long range = (unsigned long long)mx - mn + 1ull;
    int r = Nc - KKc;   // 308
    unsigned thr = mn;

    for (int pass = 0; pass < 6; pass++) {
        if (range == 1ull) { thr = (unsigned)lo; break; }
#pragma unroll
        for (int j = 0; j < 8; j++) hist[w][j * 32 + lane] = 0;
        __syncwarp();
        const unsigned lo32 = (unsigned)lo;
        const unsigned hi32 = (unsigned)(lo + range - 1ull);
        const bool small = (range <= 256ull);
        const unsigned mul = small ? 0u : (unsigned)((256ull << 32) / range);
#pragma unroll
        for (int i = 0; i < 32; i++) {
            if (u[i] >= lo32 && u[i] <= hi32) {
                unsigned d = u[i] - lo32;
                int bin = small ? (int)d : (int)__umulhi(d, mul);
                atomicAdd(&hist[w][bin], 1);
            }
        }
        __syncwarp();
        int loc[8], s = 0;
#pragma unroll
        for (int j = 0; j < 8; j++) { loc[j] = hist[w][lane * 8 + j]; s += loc[j]; }
        int c = s;
#pragma unroll
        for (int o = 1; o < 32; o <<= 1) {
            int t = __shfl_up_sync(FULL, c, o);
            if (lane >= o) c += t;
        }
        int excl = c - s;
        unsigned bal = __ballot_sync(FULL, c > r);
        int L = __ffs(bal) - 1;
        int bkt = 0, r2 = 0, cnt = 0;
        if (lane == L) {
            int a2 = excl;
#pragma unroll
            for (int j = 0; j < 8; j++) {
                if (a2 + loc[j] > r) { bkt = lane * 8 + j; r2 = r - a2; cnt = loc[j]; break; }
                a2 += loc[j];
            }
        }
        bkt = __shfl_sync(FULL, bkt, L);
        r2  = __shfl_sync(FULL, r2, L);
        cnt = __shfl_sync(FULL, cnt, L);

        unsigned long long nlo, nhi;
        if (small) {
            nlo = lo + (unsigned)bkt;
            nhi = nlo;
        } else {
            unsigned long long dl = (((unsigned long long)bkt << 32) + mul - 1ull) / mul;
            unsigned long long dh = ((((unsigned long long)(bkt + 1)) << 32) + mul - 1ull) / mul - 1ull;
            if (dh > range - 1ull) dh = range - 1ull;
            nlo = lo + dl;
            nhi = lo + dh;
        }

        if (cnt <= 32) {
            if (lane == 0) gc[w] = 0;
            __syncwarp();
            const unsigned glo = (unsigned)nlo, ghi = (unsigned)nhi;
#pragma unroll
            for (int i = 0; i < 32; i++) {
                if (u[i] >= glo && u[i] <= ghi) {
                    int p = atomicAdd(&gc[w], 1);
                    cand[w][p] = u[i];
                }
            }
            __syncwarp();
            unsigned tu = 0;
            int rk = -1;
            if (lane < cnt) {
                tu = cand[w][lane];
                rk = 0;
                for (int j = 0; j < cnt; j++) {
                    unsigned o2 = cand[w][j];
                    rk += (o2 < tu) || (o2 == tu && j < lane);
                }
            }
            unsigned who = __ballot_sync(FULL, rk == r2);
            thr = __shfl_sync(FULL, tu, __ffs(who) - 1);
            break;
        } else {
            lo = nlo;
            range = nhi - nlo + 1ull;
            r = r2;
        }
    }

    // masked softmax: overwrite u[] with exp bits (register-lean)
    const float rmax = o2f(mx);
    float sum = 0.f;
#pragma unroll
    for (int i = 0; i < 32; i++) {
        unsigned ui = u[i];
        float v = o2f(ui);
        float e = (ui >= thr) ? __expf(v - rmax) : 0.f;
        u[i] = __float_as_uint(e);
        sum += e;
    }
#pragma unroll
    for (int o = 16; o; o >>= 1) sum += __shfl_xor_sync(FULL, sum, o);
    const float inv = 1.0f / sum;
#pragma unroll
    for (int c = 0; c < 8; c++) {
        __half2 h01 = __floats2half2_rn(__uint_as_float(u[c * 4 + 0]) * inv,
                                        __uint_as_float(u[c * 4 + 1]) * inv);
        __half2 h23 = __floats2half2_rn(__uint_as_float(u[c * 4 + 2]) * inv,
                                        __uint_as_float(u[c * 4 + 3]) * inv);
        uint2 pk;
        pk.x = *(unsigned*)&h01;
        pk.y = *(unsigned*)&h23;
        *(uint2*)&pb[c * 128 + lane * 4] = pk;
    }
}

// ---------------------------------------------------------------------------
// Kernel 4: att = P @ V, fp16 MMA, cp.async 3-stage + ldmatrix
// block 128m x 64n, BK=64, 8 warps (4m x 2n); single barrier per iteration
// ---------------------------------------------------------------------------
#define AV_P   18432      // Ph: 128 rows * 144 B
#define AV_STG (AV_P + 64 * 144)
#define AV_SMEM (3 * AV_STG)

__global__ __launch_bounds__(256, 2) void k_av() {
    extern __shared__ char sm[];
    const uint32_t sb = s2u(sm);
    const int tid = threadIdx.x, lane = tid & 31, wrp = tid >> 5;
    const int wm = wrp >> 1, wn = wrp & 1;
    const int tig = lane & 3, grp = lane >> 2;
    const int bh_ = blockIdx.y, b = bh_ >> 3, h = bh_ & 7;
    const int i0 = blockIdx.x * 128;
    const __half* pg = g_p + ((size_t)bh_ * Nc + i0) * Nc;
    const __half* vt = g_vt + (size_t)bh_ * Dc * Nc;
    float acc[2][4][4] = {};

    const uint32_t a_row = (lane & 7) + ((lane >> 3) & 1) * 8;
    const uint32_t a_kof = (lane >> 4) * 8;
    const uint32_t b_row = (lane & 7) + ((lane >= 16) ? 8 : 0);
    const uint32_t b_kof = ((lane >> 3) & 1) * 8;

    auto load_stage = [&](int c, int st) {
        const uint32_t s0 = sb + st * AV_STG;
        const int kc = c * 64;
#pragma unroll
        for (int it = 0; it < 4; it++) {
            int idx = tid + it * 256;
            int row = idx >> 3, c8 = idx & 7;
            CP16(s0 + row * 144 + c8 * 16, pg + (size_t)row * Nc + kc + c8 * 8);
        }
#pragma unroll
        for (int it = 0; it < 2; it++) {
            int idx = tid + it * 256;
            int d = idx >> 3, c8 = idx & 7;
            CP16(s0 + AV_P + d * 144 + c8 * 16, vt + (size_t)d * Nc + kc + c8 * 8);
        }
        CPCOMMIT();
    };
    load_stage(0, 0);
    load_stage(1, 1);

    for (int c = 0; c < 16; c++) {
        if (c < 15) { CPWAIT1(); } else { CPWAIT0(); }
        __syncthreads();
        // prefetch stage c+2 into buffer consumed at iteration c-1 (safe after sync)
        if (c + 2 < 16) load_stage(c + 2, (c + 2) % 3);
        const uint32_t s0 = sb + (c % 3) * AV_STG;
#pragma unroll
        for (int kk = 0; kk < 64; kk += 16) {
            unsigned a[2][4];
#pragma unroll
            for (int f = 0; f < 2; f++) {
                uint32_t ra = s0 + (wm * 32 + f * 16 + a_row) * 144 + (kk + a_kof) * 2;
                ldsm4(a[f], ra);
            }
            unsigned bb[2][4];
#pragma unroll
            for (int gp = 0; gp < 2; gp++) {
                uint32_t rb = s0 + AV_P +
                              (wn * 32 + gp * 16 + b_row) * 144 + (kk + b_kof) * 2;
                ldsm4(bb[gp], rb);
            }
#pragma unroll
            for (int g = 0; g < 4; g++) {
                unsigned b0 = bb[g >> 1][(g & 1) * 2], b1 = bb[g >> 1][(g & 1) * 2 + 1];
#pragma unroll
                for (int f = 0; f < 2; f++) mma16(acc[f][g], a[f], b0, b1);
            }
        }
    }
#pragma unroll
    for (int f = 0; f < 2; f++) {
        int rr = b * Nc + i0 + wm * 32 + f * 16 + grp;
#pragma unroll
        for (int g = 0; g < 4; g++) {
            int col = h * Dc + wn * 32 + g * 8 + tig * 2;
            __half2 h0 = __floats2half2_rn(acc[f][g][0], acc[f][g][1]);
            __half2 h1 = __floats2half2_rn(acc[f][g][2], acc[f][g][3]);
            *(__half2*)&g_att[rr * INNERc + col] = h0;
            *(__half2*)&g_att[(rr + 8) * INNERc + col] = h1;
        }
    }
}

// ---------------------------------------------------------------------------
// Kernel 5: out = att @ w_out + b_out; 128m x 64n tiles, cp.async 3-stage
// ---------------------------------------------------------------------------
#define KO_A   18432
#define KO_STG (KO_A + 64 * 144)     // 27648
#define KO_SMEM (3 * KO_STG)

__global__ __launch_bounds__(256, 2) void k_out(const float* __restrict__ bias,
                                                float* __restrict__ out) {
    extern __shared__ char sm[];
    const uint32_t sb = s2u(sm);
    const int tid = threadIdx.x, lane = tid & 31, wrp = tid >> 5;
    const int wm = wrp >> 1, wn = wrp & 1;
    const int tig = lane & 3, grp = lane >> 2;
    const int row0 = blockIdx.x * 128, col0 = blockIdx.y * 64;
    float acc[2][4][4] = {};

    const uint32_t a_row = (lane & 7) + ((lane >> 3) & 1) * 8;
    const uint32_t a_kof = (lane >> 4) * 8;
    const uint32_t b_row = (lane & 7) + ((lane >= 16) ? 8 : 0);
    const uint32_t b_kof = ((lane >> 3) & 1) * 8;

    auto load_stage = [&](int c, int st) {
        const uint32_t s0 = sb + st * KO_STG;
        const int kc = c * 64;
#pragma unroll
        for (int it = 0; it < 4; it++) {
            int idx = tid + it * 256;
            int row = idx >> 3, c8 = idx & 7;
            CP16(s0 + row * 144 + c8 * 16,
                 g_att + (size_t)(row0 + row) * INNERc + kc + c8 * 8);
        }
#pragma unroll
        for (int it = 0; it < 2; it++) {
            int idx = tid + it * 256;
            int n = idx >> 3, c8 = idx & 7;
            CP16(s0 + KO_A + n * 144 + c8 * 16,
                 g_wo + (size_t)(col0 + n) * INNERc + kc + c8 * 8);
        }
        CPCOMMIT();
    };
    load_stage(0, 0);
    load_stage(1, 1);

    for (int c = 0; c < 8; c++) {
        if (c < 7) { CPWAIT1(); } else { CPWAIT0(); }
        __syncthreads();
        if (c + 2 < 8) load_stage(c + 2, (c + 2) % 3);
        const uint32_t s0 = sb + (c % 3) * KO_STG;
#pragma unroll
        for (int kk = 0; kk < 64; kk += 16) {
            unsigned a[2][4];
#pragma unroll
            for (int f = 0; f < 2; f++) {
                uint32_t ra = s0 + (wm * 32 + f * 16 + a_row) * 144 + (kk + a_kof) * 2;
                ldsm4(a[f], ra);
            }
            unsigned bb[2][4];
#pragma unroll
            for (int gp = 0; gp < 2; gp++) {
                uint32_t rb = s0 + KO_A +
                              (wn * 32 + gp * 16 + b_row) * 144 + (kk + b_kof) * 2;
                ldsm4(bb[gp], rb);
            }
#pragma unroll
            for (int g = 0; g < 4; g++) {
                unsigned b0 = bb[g >> 1][(g & 1) * 2], b1 = bb[g >> 1][(g & 1) * 2 + 1];
#pragma unroll
                for (int f = 0; f < 2; f++) mma16(acc[f][g], a[f], b0, b1);
            }
        }
    }
#pragma unroll
    for (int f = 0; f < 2; f++) {
        int row = row0 + wm * 32 + f * 16 + grp;
#pragma unroll
        for (int g = 0; g < 4; g++) {
            int col = col0 + wn * 32 + g * 8 + tig * 2;
            float b0 = bias[col], b1 = bias[col + 1];
            *(float2*)&out[(size_t)row * DIMc + col] =
                make_float2(acc[f][g][0] + b0, acc[f][g][1] + b1);
            *(float2*)&out[(size_t)(row + 8) * DIMc + col] =
                make_float2(acc[f][g][2] + b0, acc[f][g][3] + b1);
        }
    }
}

// ---------------------------------------------------------------------------
extern "C" void kernel_launch(void* const* d_in, const int* in_sizes, int n_in,
                              void* d_out, int out_size) {
    const float* x     = (const float*)d_in[0];  // [4,1024,512]
    const float* w_qkv = (const float*)d_in[1];  // [512,1536]
    const float* w_out = (const float*)d_in[2];  // [512,512]
    const float* b_out = (const float*)d_in[3];  // [512]
    float* out = (float*)d_out;                  // [4,1024,512]

    cudaFuncSetAttribute(k_qkv, cudaFuncAttributeMaxDynamicSharedMemorySize, QK_SMEM);
    cudaFuncSetAttribute(k_dots, cudaFuncAttributeMaxDynamicSharedMemorySize, QK_SMEM);
    cudaFuncSetAttribute(k_av, cudaFuncAttributeMaxDynamicSharedMemorySize, AV_SMEM);
    cudaFuncSetAttribute(k_out, cudaFuncAttributeMaxDynamicSharedMemorySize, KO_SMEM);

    k_prep_x<<<(Bc * Nc * DIMc / 4) / 256, 256>>>(x);
    k_prep_wq<<<dim3(QKV3c / 32, DIMc / 32), 256>>>(w_qkv);
    k_prep_wo<<<dim3(DIMc / 32, INNERc / 32), 256>>>(w_out);
    k_qkv<<<dim3(QKV3c / 128, (Bc * Nc) / 128), 256, QK_SMEM>>>();
    k_dots<<<dim3(Nc / 128, Nc / 128, BHc), 256, QK_SMEM>>>();
    k_topk<<<(BHc * Nc) / 8, 256>>>();
    k_av<<<dim3(Nc / 128, BHc), 256, AV_SMEM>>>();
    k_out<<<dim3((Bc * Nc) / 128, DIMc / 64), 256, KO_SMEM>>>(b_out, out);
}

// round 16
// speedup vs baseline: 1.6204x; 1.0138x over previous
#include <cuda_runtime.h>
#include <cuda_fp16.h>
#include <cstdint>

#define Bc     4
#define Nc     1024
#define Hc     8
#define Dc     64
#define DIMc   512
#define INNERc 512
#define QKV3c  1536
#define BHc    32
#define KKc    716
#define SCALEc 0.125f

// Scratch (device globals: no allocations allowed)
__device__ __half g_xh[Bc * Nc * DIMc], g_xl[Bc * Nc * DIMc];      // x split
__device__ __half g_wqh[QKV3c * DIMc], g_wql[QKV3c * DIMc];        // w_qkv^T split [n][k]
__device__ __half g_wo[DIMc * INNERc];                             // w_out^T fp16 [n][k]
__device__ __half g_qh[Bc * Nc * INNERc], g_ql[Bc * Nc * INNERc];  // Q*scale split
__device__ __half g_kh[Bc * Nc * INNERc], g_kl[Bc * Nc * INNERc];  // K split
__device__ __half g_vt[(size_t)BHc * Dc * Nc];                     // V^T [bh][d][n]
__device__ float  g_dots[(size_t)BHc * Nc * Nc];                   // fp32 pre-softmax
__device__ __half g_p[(size_t)BHc * Nc * Nc];                      // fp16 post-softmax
__device__ __half g_att[Bc * Nc * INNERc];                         // fp16

// ---------------------------------------------------------------------------
// helpers
// ---------------------------------------------------------------------------
__device__ __forceinline__ void split_h(float v, __half& hi, __half& lo) {
    __half h = __float2half_rn(v);
    hi = h;
    lo = __float2half_rn(v - __half2float(h));
}
__device__ __forceinline__ void mma16(float* c, const unsigned* a,
                                      unsigned b0, unsigned b1) {
    asm volatile(
        "mma.sync.aligned.m16n8k16.row.col.f32.f16.f16.f32 "
        "{%0,%1,%2,%3}, {%4,%5,%6,%7}, {%8,%9}, {%0,%1,%2,%3};"
        : "+f"(c[0]), "+f"(c[1]), "+f"(c[2]), "+f"(c[3])
        : "r"(a[0]), "r"(a[1]), "r"(a[2]), "r"(a[3]), "r"(b0), "r"(b1));
}
__device__ __forceinline__ unsigned f2o(float x) {
    unsigned u = __float_as_uint(x);
    return (u & 0x80000000u) ? ~u : (u | 0x80000000u);
}
__device__ __forceinline__ float o2f(unsigned u) {
    unsigned f = (u & 0x80000000u) ? (u & 0x7fffffffu) : ~u;
    return __uint_as_float(f);
}
__device__ __forceinline__ uint32_t s2u(const void* p) {
    uint32_t a;
    asm("{ .reg .u64 t; cvta.to.shared.u64 t, %1; cvt.u32.u64 %0, t; }"
        : "=r"(a) : "l"(p));
    return a;
}
#define CP16(sa, gp) \
    asm volatile("cp.async.cg.shared.global [%0], [%1], 16;" :: "r"(sa), "l"(gp))
#define CPCOMMIT() asm volatile("cp.async.commit_group;")
#define CPWAIT1()  asm volatile("cp.async.wait_group 1;")
#define CPWAIT0()  asm volatile("cp.async.wait_group 0;")
__device__ __forceinline__ void ldsm4(unsigned* r, uint32_t a) {
    asm volatile("ldmatrix.sync.aligned.m8n8.x4.shared.b16 {%0,%1,%2,%3}, [%4];"
                 : "=r"(r[0]), "=r"(r[1]), "=r"(r[2]), "=r"(r[3]) : "r"(a));
}

// ---------------------------------------------------------------------------
// Prep kernels: split/convert inputs once
// ---------------------------------------------------------------------------
__global__ __launch_bounds__(256) void k_prep_x(const float* __restrict__ x) {
    int idx = blockIdx.x * 256 + threadIdx.x;
    float4 v = ((const float4*)x)[idx];
    float vv[4] = {v.x, v.y, v.z, v.w};
    __half hh[4], ll[4];
#pragma unroll
    for (int i = 0; i < 4; i++) split_h(vv[i], hh[i], ll[i]);
    ((uint2*)g_xh)[idx] = *(uint2*)hh;
    ((uint2*)g_xl)[idx] = *(uint2*)ll;
}

__global__ __launch_bounds__(256) void k_prep_wq(const float* __restrict__ w) {
    __shared__ float t[32][33];
    const int tx = threadIdx.x & 31, ty = threadIdx.x >> 5;
    const int n0 = blockIdx.x * 32, k0 = blockIdx.y * 32;
#pragma unroll
    for (int i = 0; i < 4; i++)
        t[ty + i * 8][tx] = w[(size_t)(k0 + ty + i * 8) * QKV3c + n0 + tx];
    __syncthreads();
#pragma unroll
    for (int i = 0; i < 4; i++) {
        int n = n0 + ty + i * 8;
        float v = t[tx][ty + i * 8];
        __half h, l;
        split_h(v, h, l);
        g_wqh[(size_t)n * DIMc + k0 + tx] = h;
        g_wql[(size_t)n * DIMc + k0 + tx] = l;
    }
}

__global__ __launch_bounds__(256) void k_prep_wo(const float* __restrict__ w) {
    __shared__ float t[32][33];
    const int tx = threadIdx.x & 31, ty = threadIdx.x >> 5;
    const int n0 = blockIdx.x * 32, k0 = blockIdx.y * 32;
#pragma unroll
    for (int i = 0; i < 4; i++)
        t[ty + i * 8][tx] = w[(size_t)(k0 + ty + i * 8) * DIMc + n0 + tx];
    __syncthreads();
#pragma unroll
    for (int i = 0; i < 4; i++) {
        int n = n0 + ty + i * 8;
        g_wo[(size_t)n * INNERc + k0 + tx] = __float2half(t[tx][ty + i * 8]);
    }
}

// ---------------------------------------------------------------------------
// Kernel 1: qkv GEMM, fp16-split, cp.async 2-stage + ldmatrix
// 3-pass MMA scheduling (RAW distance 16); V CTAs skip pass-1.
// ---------------------------------------------------------------------------
#define QK_ARR 10240      // 128 rows * 80 B
#define QK_STG (4 * QK_ARR)
#define QK_SMEM (2 * QK_STG)

__global__ __launch_bounds__(256, 2) void k_qkv() {
    extern __shared__ char sm[];
    const uint32_t sb = s2u(sm);
    const int tid = threadIdx.x, lane = tid & 31, wrp = tid >> 5;
    const int wm = wrp & 1, wn = wrp >> 1;
    const int tig = lane & 3, grp = lane >> 2;
    const int row0 = blockIdx.y * 128, col0 = blockIdx.x * 128;
    const bool isV = (blockIdx.x >> 2) == 2;
    float acc[4][4][4] = {};

    const int lrow = tid >> 2, lq = tid & 3;
    const uint32_t a_row = (lane & 7) + ((lane >> 3) & 1) * 8;
    const uint32_t a_kof = (lane >> 4) * 8;
    const uint32_t b_row = (lane & 7) + ((lane >= 16) ? 8 : 0);
    const uint32_t b_kof = ((lane >> 3) & 1) * 8;

    auto load_stage = [&](int c, int st) {
        const uint32_t s0 = sb + st * QK_STG;
        const int kt = c * 32;
#pragma unroll
        for (int it = 0; it < 2; it++) {
            int row = lrow + it * 64;
            uint32_t so = row * 80 + lq * 16;
            size_t ga = (size_t)(row0 + row) * DIMc + kt + lq * 8;
            CP16(s0 + so, g_xh + ga);
            CP16(s0 + QK_ARR + so, g_xl + ga);
            size_t gb = (size_t)(col0 + row) * DIMc + kt + lq * 8;
            CP16(s0 + 2 * QK_ARR + so, g_wqh + gb);
            CP16(s0 + 3 * QK_ARR + so, g_wql + gb);
        }
        CPCOMMIT();
    };
    load_stage(0, 0);
    load_stage(1, 1);

    for (int c = 0; c < 16; c++) {
        if (c < 15) { CPWAIT1(); } else { CPWAIT0(); }
        __syncthreads();
        const uint32_t s0 = sb + (c & 1) * QK_STG;
#pragma unroll
        for (int kk = 0; kk < 32; kk += 16) {
            unsigned ah[4][4], al[4][4];
#pragma unroll
            for (int f = 0; f < 4; f++) {
                uint32_t ra = s0 + (wm * 64 + f * 16 + a_row) * 80 + (kk + a_kof) * 2;
                ldsm4(ah[f], ra);
                ldsm4(al[f], ra + QK_ARR);
            }
            unsigned bh[2][4], bl[2][4];
#pragma unroll
            for (int gp = 0; gp < 2; gp++) {
                uint32_t rb = s0 + 2 * QK_ARR +
                              (wn * 32 + gp * 16 + b_row) * 80 + (kk + b_kof) * 2;
                ldsm4(bh[gp], rb);
                ldsm4(bl[gp], rb + QK_ARR);
            }
            // pass 0: ah x bh  (all 16 accumulators, RAW distance 16)
#pragma unroll
            for (int g = 0; g < 4; g++) {
                unsigned h0 = bh[g >> 1][(g & 1) * 2], h1 = bh[g >> 1][(g & 1) * 2 + 1];
#pragma unroll
                for (int f = 0; f < 4; f++) mma16(acc[f][g], ah[f], h0, h1);
            }
            // pass 1: ah x bl  (skipped for V)
            if (!isV) {
#pragma unroll
                for (int g = 0; g < 4; g++) {
                    unsigned l0 = bl[g >> 1][(g & 1) * 2], l1 = bl[g >> 1][(g & 1) * 2 + 1];
#pragma unroll
                    for (int f = 0; f < 4; f++) mma16(acc[f][g], ah[f], l0, l1);
                }
            }
            // pass 2: al x bh
#pragma unroll
            for (int g = 0; g < 4; g++) {
                unsigned h0 = bh[g >> 1][(g & 1) * 2], h1 = bh[g >> 1][(g & 1) * 2 + 1];
#pragma unroll
                for (int f = 0; f < 4; f++) mma16(acc[f][g], al[f], h0, h1);
            }
        }
        __syncthreads();
        if (c + 2 < 16) load_stage(c + 2, c & 1);
    }

    const int sec = blockIdx.x >> 2;            // 0=Q, 1=K, 2=V
    const int csec = (blockIdx.x & 3) * 128;
#pragma unroll
    for (int f = 0; f < 4; f++) {
        int row = row0 + wm * 64 + f * 16 + grp;
#pragma unroll
        for (int g = 0; g < 4; g++) {
            int cl = csec + wn * 32 + g * 8 + tig * 2;
            if (sec == 0) {
                __half h0, l0, h1, l1, h2, l2, h3, l3;
                split_h(acc[f][g][0] * SCALEc, h0, l0);
                split_h(acc[f][g][1] * SCALEc, h1, l1);
                split_h(acc[f][g][2] * SCALEc, h2, l2);
                split_h(acc[f][g][3] * SCALEc, h3, l3);
                *(__half2*)&g_qh[(size_t)row * INNERc + cl] = __halves2half2(h0, h1);
                *(__half2*)&g_ql[(size_t)row * INNERc + cl] = __halves2half2(l0, l1);
                *(__half2*)&g_qh[(size_t)(row + 8) * INNERc + cl] = __halves2half2(h2, h3);
                *(__half2*)&g_ql[(size_t)(row + 8) * INNERc + cl] = __halves2half2(l2, l3);
            } else if (sec == 1) {
                __half h0, l0, h1, l1, h2, l2, h3, l3;
                split_h(acc[f][g][0], h0, l0);
                split_h(acc[f][g][1], h1, l1);
                split_h(acc[f][g][2], h2, l2);
                split_h(acc[f][g][3], h3, l3);
                *(__half2*)&g_kh[(size_t)row * INNERc + cl] = __halves2half2(h0, h1);
                *(__half2*)&g_kl[(size_t)row * INNERc + cl] = __halves2half2(l0, l1);
                *(__half2*)&g_kh[(size_t)(row + 8) * INNERc + cl] = __halves2half2(h2, h3);
                *(__half2*)&g_kl[(size_t)(row + 8) * INNERc + cl] = __halves2half2(l2, l3);
            } else {
                int h = cl >> 6, d = cl & 63;
                int b = row >> 10, n = row & 1023;
                size_t base = ((size_t)(b * 8 + h) * 64 + d) * 1024 + n;
                g_vt[base]            = __float2half(acc[f][g][0]);
                g_vt[base + 1024]     = __float2half(acc[f][g][1]);
                g_vt[base + 8]        = __float2half(acc[f][g][2]);
                g_vt[base + 1024 + 8] = __float2half(acc[f][g][3]);
            }
        }
    }
}

// ---------------------------------------------------------------------------
// Kernel 2: dots = (Q*scale) @ K^T, fp16-split, 3-pass MMA scheduling
// ---------------------------------------------------------------------------
__global__ __launch_bounds__(256, 2) void k_dots() {
    extern __shared__ char sm[];
    const uint32_t sb = s2u(sm);
    const int tid = threadIdx.x, lane = tid & 31, wrp = tid >> 5;
    const int wm = wrp & 1, wn = wrp >> 1;
    const int tig = lane & 3, grp = lane >> 2;
    const int bh_ = blockIdx.z, b = bh_ >> 3, h = bh_ & 7;
    const int i0 = blockIdx.y * 128, j0 = blockIdx.x * 128;
    float acc[4][4][4] = {};

    const int lrow = tid >> 2, lq = tid & 3;
    const uint32_t a_row = (lane & 7) + ((lane >> 3) & 1) * 8;
    const uint32_t a_kof = (lane >> 4) * 8;
    const uint32_t b_row = (lane & 7) + ((lane >= 16) ? 8 : 0);
    const uint32_t b_kof = ((lane >> 3) & 1) * 8;

    auto load_stage = [&](int c, int st) {
        const uint32_t s0 = sb + st * QK_STG;
        const int kt = c * 32;
#pragma unroll
        for (int it = 0; it < 2; it++) {
            int row = lrow + it * 64;
            uint32_t so = row * 80 + lq * 16;
            size_t ga = (size_t)(b * Nc + i0 + row) * INNERc + h * Dc + kt + lq * 8;
            CP16(s0 + so, g_qh + ga);
            CP16(s0 + QK_ARR + so, g_ql + ga);
            size_t gb = (size_t)(b * Nc + j0 + row) * INNERc + h * Dc + kt + lq * 8;
            CP16(s0 + 2 * QK_ARR + so, g_kh + gb);
            CP16(s0 + 3 * QK_ARR + so, g_kl + gb);
        }
        CPCOMMIT();
    };
    load_stage(0, 0);
    load_stage(1, 1);

    for (int c = 0; c < 2; c++) {
        if (c == 0) { CPWAIT1(); } else { CPWAIT0(); }
        __syncthreads();
        const uint32_t s0 = sb + c * QK_STG;
#pragma unroll
        for (int kk = 0; kk < 32; kk += 16) {
            unsigned ah[4][4], al[4][4];
#pragma unroll
            for (int f = 0; f < 4; f++) {
                uint32_t ra = s0 + (wm * 64 + f * 16 + a_row) * 80 + (kk + a_kof) * 2;
                ldsm4(ah[f], ra);
                ldsm4(al[f], ra + QK_ARR);
            }
            unsigned bh[2][4], bl[2][4];
#pragma unroll
            for (int gp = 0; gp < 2; gp++) {
                uint32_t rb = s0 + 2 * QK_ARR +
                              (wn * 32 + gp * 16 + b_row) * 80 + (kk + b_kof) * 2;
                ldsm4(bh[gp], rb);
                ldsm4(bl[gp], rb + QK_ARR);
            }
            // pass 0: ah x bh
#pragma unroll
            for (int g = 0; g < 4; g++) {
                unsigned h0 = bh[g >> 1][(g & 1) * 2], h1 = bh[g >> 1][(g & 1) * 2 + 1];
#pragma unroll
                for (int f = 0; f < 4; f++) mma16(acc[f][g], ah[f], h0, h1);
            }
            // pass 1: ah x bl
#pragma unroll
            for (int g = 0; g < 4; g++) {
                unsigned l0 = bl[g >> 1][(g & 1) * 2], l1 = bl[g >> 1][(g & 1) * 2 + 1];
#pragma unroll
                for (int f = 0; f < 4; f++) mma16(acc[f][g], ah[f], l0, l1);
            }
            // pass 2: al x bh
#pragma unroll
            for (int g = 0; g < 4; g++) {
                unsigned h0 = bh[g >> 1][(g & 1) * 2], h1 = bh[g >> 1][(g & 1) * 2 + 1];
#pragma unroll
                for (int f = 0; f < 4; f++) mma16(acc[f][g], al[f], h0, h1);
            }
        }
        __syncthreads();
    }
    float* out = g_dots + (size_t)bh_ * Nc * Nc;
#pragma unroll
    for (int f = 0; f < 4; f++) {
        int row = i0 + wm * 64 + f * 16 + grp;
#pragma unroll
        for (int g = 0; g < 4; g++) {
            int col = j0 + wn * 32 + g * 8 + tig * 2;
            *(float2*)&out[(size_t)row * Nc + col] =
                make_float2(acc[f][g][0], acc[f][g][1]);
            *(float2*)&out[(size_t)(row + 8) * Nc + col] =
                make_float2(acc[f][g][2], acc[f][g][3]);
        }
    }
}

// ---------------------------------------------------------------------------
// Kernel 3: warp-per-row exact top-KK + masked softmax; 256-bin radix pass
// ---------------------------------------------------------------------------
__global__ __launch_bounds__(256) void k_topk() {
    __shared__ int      hist[8][256];
    __shared__ unsigned cand[8][32];
    __shared__ int      gc[8];

    const unsigned FULL = 0xffffffffu;
    const int tid = threadIdx.x, lane = tid & 31, w = tid >> 5;
    const size_t row = (size_t)blockIdx.x * 8 + w;
    const float* base = g_dots + row * Nc;
    __half* pb = g_p + row * Nc;

    unsigned u[32];
#pragma unroll
    for (int c = 0; c < 8; c++) {
        float4 v4 = *(const float4*)&base[c * 128 + lane * 4];
        u[c * 4 + 0] = f2o(v4.x);
        u[c * 4 + 1] = f2o(v4.y);
        u[c * 4 + 2] = f2o(v4.z);
        u[c * 4 + 3] = f2o(v4.w);
    }

    unsigned mn = u[0], mx = u[0];
#pragma unroll
    for (int i = 1; i < 32; i++) { mn = min(mn, u[i]); mx = max(mx, u[i]); }
#pragma unroll
    for (int o = 16; o; o >>= 1) {
        mn = min(mn, __shfl_xor_sync(FULL, mn, o));
        mx = max(mx, __shfl_xor_sync(FULL, mx, o));
    }

    unsigned long long lo = mn;
    unsigned long long range = (unsigned long long)mx - mn + 1ull;
    int r = Nc - KKc;   // 308
    unsigned thr = mn;

    for (int pass = 0; pass < 6; pass++) {
        if (range == 1ull) { thr = (unsigned)lo; break; }
#pragma unroll
        for (int j = 0; j < 8; j++) hist[w][j * 32 + lane] = 0;
        __syncwarp();
        const unsigned lo32 = (unsigned)lo;
        const unsigned hi32 = (unsigned)(lo + range - 1ull);
        const bool small = (range <= 256ull);
        const unsigned mul = small ? 0u : (unsigned)((256ull << 32) / range);
#pragma unroll
        for (int i = 0; i < 32; i++) {
            if (u[i] >= lo32 && u[i] <= hi32) {
                unsigned d = u[i] - lo32;
                int bin = small ? (int)d : (int)__umulhi(d, mul);
                atomicAdd(&hist[w][bin], 1);
            }
        }
        __syncwarp();
        int loc[8], s = 0;
#pragma unroll
        for (int j = 0; j < 8; j++) { loc[j] = hist[w][lane * 8 + j]; s += loc[j]; }
        int c = s;
#pragma unroll
        for (int o = 1; o < 32; o <<= 1) {
            int t = __shfl_up_sync(FULL, c, o);
            if (lane >= o) c += t;
        }
        int excl = c - s;
        unsigned bal = __ballot_sync(FULL, c > r);
        int L = __ffs(bal) - 1;
        int bkt = 0, r2 = 0, cnt = 0;
        if (lane == L) {
            int a2 = excl;
#pragma unroll
            for (int j = 0; j < 8; j++) {
                if (a2 + loc[j] > r) { bkt = lane * 8 + j; r2 = r - a2; cnt = loc[j]; break; }
                a2 += loc[j];
            }
        }
        bkt = __shfl_sync(FULL, bkt, L);
        r2  = __shfl_sync(FULL, r2, L);
        cnt = __shfl_sync(FULL, cnt, L);

        unsigned long long nlo, nhi;
        if (small) {
            nlo = lo + (unsigned)bkt;
            nhi = nlo;
        } else {
            unsigned long long dl = (((unsigned long long)bkt << 32) + mul - 1ull) / mul;
            unsigned long long dh = ((((unsigned long long)(bkt + 1)) << 32) + mul - 1ull) / mul - 1ull;
            if (dh > range - 1ull) dh = range - 1ull;
            nlo = lo + dl;
            nhi = lo + dh;
        }

        if (cnt <= 32) {
            if (lane == 0) gc[w] = 0;
            __syncwarp();
            const unsigned glo = (unsigned)nlo, ghi = (unsigned)nhi;
#pragma unroll
            for (int i = 0; i < 32; i++) {
                if (u[i] >= glo && u[i] <= ghi) {
                    int p = atomicAdd(&gc[w], 1);
                    cand[w][p] = u[i];
                }
            }
            __syncwarp();
            unsigned tu = 0;
            int rk = -1;
            if (lane < cnt) {
                tu = cand[w][lane];
                rk = 0;
                for (int j = 0; j < cnt; j++) {
                    unsigned o2 = cand[w][j];
                    rk += (o2 < tu) || (o2 == tu && j < lane);
                }
            }
            unsigned who = __ballot_sync(FULL, rk == r2);
            thr = __shfl_sync(FULL, tu, __ffs(who) - 1);
            break;
        } else {
            lo = nlo;
            range = nhi - nlo + 1ull;
            r = r2;
        }
    }

    // masked softmax: overwrite u[] with exp bits (register-lean)
    const float rmax = o2f(mx);
    float sum = 0.f;
#pragma unroll
    for (int i = 0; i < 32; i++) {
        unsigned ui = u[i];
        float v = o2f(ui);
        float e = (ui >= thr) ? __expf(v - rmax) : 0.f;
        u[i] = __float_as_uint(e);
        sum += e;
    }
#pragma unroll
    for (int o = 16; o; o >>= 1) sum += __shfl_xor_sync(FULL, sum, o);
    const float inv = 1.0f / sum;
#pragma unroll
    for (int c = 0; c < 8; c++) {
        __half2 h01 = __floats2half2_rn(__uint_as_float(u[c * 4 + 0]) * inv,
                                        __uint_as_float(u[c * 4 + 1]) * inv);
        __half2 h23 = __floats2half2_rn(__uint_as_float(u[c * 4 + 2]) * inv,
                                        __uint_as_float(u[c * 4 + 3]) * inv);
        uint2 pk;
        pk.x = *(unsigned*)&h01;
        pk.y = *(unsigned*)&h23;
        *(uint2*)&pb[c * 128 + lane * 4] = pk;
    }
}

// ---------------------------------------------------------------------------
// Kernel 4: att = P @ V, fp16 MMA, cp.async 3-stage + ldmatrix
// ---------------------------------------------------------------------------
#define AV_P   18432      // Ph: 128 rows * 144 B
#define AV_STG (AV_P + 64 * 144)
#define AV_SMEM (3 * AV_STG)

__global__ __launch_bounds__(256, 2) void k_av() {
    extern __shared__ char sm[];
    const uint32_t sb = s2u(sm);
    const int tid = threadIdx.x, lane = tid & 31, wrp = tid >> 5;
    const int wm = wrp >> 1, wn = wrp & 1;
    const int tig = lane & 3, grp = lane >> 2;
    const int bh_ = blockIdx.y, b = bh_ >> 3, h = bh_ & 7;
    const int i0 = blockIdx.x * 128;
    const __half* pg = g_p + ((size_t)bh_ * Nc + i0) * Nc;
    const __half* vt = g_vt + (size_t)bh_ * Dc * Nc;
    float acc[2][4][4] = {};

    const uint32_t a_row = (lane & 7) + ((lane >> 3) & 1) * 8;
    const uint32_t a_kof = (lane >> 4) * 8;
    const uint32_t b_row = (lane & 7) + ((lane >= 16) ? 8 : 0);
    const uint32_t b_kof = ((lane >> 3) & 1) * 8;

    auto load_stage = [&](int c, int st) {
        const uint32_t s0 = sb + st * AV_STG;
        const int kc = c * 64;
#pragma unroll
        for (int it = 0; it < 4; it++) {
            int idx = tid + it * 256;
            int row = idx >> 3, c8 = idx & 7;
            CP16(s0 + row * 144 + c8 * 16, pg + (size_t)row * Nc + kc + c8 * 8);
        }
#pragma unroll
        for (int it = 0; it < 2; it++) {
            int idx = tid + it * 256;
            int d = idx >> 3, c8 = idx & 7;
            CP16(s0 + AV_P + d * 144 + c8 * 16, vt + (size_t)d * Nc + kc + c8 * 8);
        }
        CPCOMMIT();
    };
    load_stage(0, 0);
    load_stage(1, 1);

    for (int c = 0; c < 16; c++) {
        if (c < 15) { CPWAIT1(); } else { CPWAIT0(); }
        __syncthreads();
        if (c + 2 < 16) load_stage(c + 2, (c + 2) % 3);
        const uint32_t s0 = sb + (c % 3) * AV_STG;
#pragma unroll
        for (int kk = 0; kk < 64; kk += 16) {
            unsigned a[2][4];
#pragma unroll
            for (int f = 0; f < 2; f++) {
                uint32_t ra = s0 + (wm * 32 + f * 16 + a_row) * 144 + (kk + a_kof) * 2;
                ldsm4(a[f], ra);
            }
            unsigned bb[2][4];
#pragma unroll
            for (int gp = 0; gp < 2; gp++) {
                uint32_t rb = s0 + AV_P +
                              (wn * 32 + gp * 16 + b_row) * 144 + (kk + b_kof) * 2;
                ldsm4(bb[gp], rb);
            }
#pragma unroll
            for (int g = 0; g < 4; g++) {
                unsigned b0 = bb[g >> 1][(g & 1) * 2], b1 = bb[g >> 1][(g & 1) * 2 + 1];
#pragma unroll
                for (int f = 0; f < 2; f++) mma16(acc[f][g], a[f], b0, b1);
            }
        }
    }
#pragma unroll
    for (int f = 0; f < 2; f++) {
        int rr = b * Nc + i0 + wm * 32 + f * 16 + grp;
#pragma unroll
        for (int g = 0; g < 4; g++) {
            int col = h * Dc + wn * 32 + g * 8 + tig * 2;
            __half2 h0 = __floats2half2_rn(acc[f][g][0], acc[f][g][1]);
            __half2 h1 = __floats2half2_rn(acc[f][g][2], acc[f][g][3]);
            *(__half2*)&g_att[rr * INNERc + col] = h0;
            *(__half2*)&g_att[(rr + 8) * INNERc + col] = h1;
        }
    }
}

// ---------------------------------------------------------------------------
// Kernel 5: out = att @ w_out + b_out; 128m x 64n tiles, cp.async 3-stage
// ---------------------------------------------------------------------------
#define KO_A   18432
#define KO_STG (KO_A + 64 * 144)     // 27648
#define KO_SMEM (3 * KO_STG)

__global__ __launch_bounds__(256, 2) void k_out(const float* __restrict__ bias,
                                                float* __restrict__ out) {
    extern __shared__ char sm[];
    const uint32_t sb = s2u(sm);
    const int tid = threadIdx.x, lane = tid & 31, wrp = tid >> 5;
    const int wm = wrp >> 1, wn = wrp & 1;
    const int tig = lane & 3, grp = lane >> 2;
    const int row0 = blockIdx.x * 128, col0 = blockIdx.y * 64;
    float acc[2][4][4] = {};

    const uint32_t a_row = (lane & 7) + ((lane >> 3) & 1) * 8;
    const uint32_t a_kof = (lane >> 4) * 8;
    const uint32_t b_row = (lane & 7) + ((lane >= 16) ? 8 : 0);
    const uint32_t b_kof = ((lane >> 3) & 1) * 8;

    auto load_stage = [&](int c, int st) {
        const uint32_t s0 = sb + st * KO_STG;
        const int kc = c * 64;
#pragma unroll
        for (int it = 0; it < 4; it++) {
            int idx = tid + it * 256;
            int row = idx >> 3, c8 = idx & 7;
            CP16(s0 + row * 144 + c8 * 16,
                 g_att + (size_t)(row0 + row) * INNERc + kc + c8 * 8);
        }
#pragma unroll
        for (int it = 0; it < 2; it++) {
            int idx = tid + it * 256;
            int n = idx >> 3, c8 = idx & 7;
            CP16(s0 + KO_A + n * 144 + c8 * 16,
                 g_wo + (size_t)(col0 + n) * INNERc + kc + c8 * 8);
        }
        CPCOMMIT();
    };
    load_stage(0, 0);
    load_stage(1, 1);

    for (int c = 0; c < 8; c++) {
        if (c < 7) { CPWAIT1(); } else { CPWAIT0(); }
        __syncthreads();
        if (c + 2 < 8) load_stage(c + 2, (c + 2) % 3);
        const uint32_t s0 = sb + (c % 3) * KO_STG;
#pragma unroll
        for (int kk = 0; kk < 64; kk += 16) {
            unsigned a[2][4];
#pragma unroll
            for (int f = 0; f < 2; f++) {
                uint32_t ra = s0 + (wm * 32 + f * 16 + a_row) * 144 + (kk + a_kof) * 2;
                ldsm4(a[f], ra);
            }
            unsigned bb[2][4];
#pragma unroll
            for (int gp = 0; gp < 2; gp++) {
                uint32_t rb = s0 + KO_A +
                              (wn * 32 + gp * 16 + b_row) * 144 + (kk + b_kof) * 2;
                ldsm4(bb[gp], rb);
            }
#pragma unroll
            for (int g = 0; g < 4; g++) {
                unsigned b0 = bb[g >> 1][(g & 1) * 2], b1 = bb[g >> 1][(g & 1) * 2 + 1];
#pragma unroll
                for (int f = 0; f < 2; f++) mma16(acc[f][g], a[f], b0, b1);
            }
        }
    }
#pragma unroll
    for (int f = 0; f < 2; f++) {
        int row = row0 + wm * 32 + f * 16 + grp;
#pragma unroll
        for (int g = 0; g < 4; g++) {
            int col = col0 + wn * 32 + g * 8 + tig * 2;
            float b0 = bias[col], b1 = bias[col + 1];
            *(float2*)&out[(size_t)row * DIMc + col] =
                make_float2(acc[f][g][0] + b0, acc[f][g][1] + b1);
            *(float2*)&out[(size_t)(row + 8) * DIMc + col] =
                make_float2(acc[f][g][2] + b0, acc[f][g][3] + b1);
        }
    }
}

// ---------------------------------------------------------------------------
extern "C" void kernel_launch(void* const* d_in, const int* in_sizes, int n_in,
                              void* d_out, int out_size) {
    const float* x     = (const float*)d_in[0];  // [4,1024,512]
    const float* w_qkv = (const float*)d_in[1];  // [512,1536]
    const float* w_out = (const float*)d_in[2];  // [512,512]
    const float* b_out = (const float*)d_in[3];  // [512]
    float* out = (float*)d_out;                  // [4,1024,512]

    cudaFuncSetAttribute(k_qkv, cudaFuncAttributeMaxDynamicSharedMemorySize, QK_SMEM);
    cudaFuncSetAttribute(k_dots, cudaFuncAttributeMaxDynamicSharedMemorySize, QK_SMEM);
    cudaFuncSetAttribute(k_av, cudaFuncAttributeMaxDynamicSharedMemorySize, AV_SMEM);
    cudaFuncSetAttribute(k_out, cudaFuncAttributeMaxDynamicSharedMemorySize, KO_SMEM);

    k_prep_x<<<(Bc * Nc * DIMc / 4) / 256, 256>>>(x);
    k_prep_wq<<<dim3(QKV3c / 32, DIMc / 32), 256>>>(w_qkv);
    k_prep_wo<<<dim3(DIMc / 32, INNERc / 32), 256>>>(w_out);
    k_qkv<<<dim3(QKV3c / 128, (Bc * Nc) / 128), 256, QK_SMEM>>>();
    k_dots<<<dim3(Nc / 128, Nc / 128, BHc), 256, QK_SMEM>>>();
    k_topk<<<(BHc * Nc) / 8, 256>>>();
    k_av<<<dim3(Nc / 128, BHc), 256, AV_SMEM>>>();
    k_out<<<dim3((Bc * Nc) / 128, DIMc / 64), 256, KO_SMEM>>>(b_out, out);
}